// round 8
// baseline (speedup 1.0000x reference)
#include <cuda_runtime.h>
#include <cuda_bf16.h>
#include <cstdint>

// Problem constants
constexpr int T_DIM = 256;
constexpr int B_DIM = 256;
constexpr int IN_DIM = 1024;
constexpr int H_DIM = 1024;
constexpr int M1 = T_DIM * B_DIM;
constexpr int BH = B_DIM * H_DIM;

// ---------------------------------------------------------------------------
// Device globals (static allocations - allowed)
// ---------------------------------------------------------------------------
__device__ int g_cnt[T_DIM];                       // per-step barrier counters
__device__ __nv_bfloat16 g_Wh_hi[H_DIM * H_DIM];   // Wh split hi
__device__ __nv_bfloat16 g_Wh_lo[H_DIM * H_DIM];   // Wh split lo
__device__ __nv_bfloat16 g_h_hi[2][BH];            // h split hi (step parity)
__device__ __nv_bfloat16 g_h_lo[2][BH];            // h split lo

constexpr int N_CTAS = 128;    // 32 n-tiles x 4 m-tiles

// Shared memory layout (bytes) for the persistent kernel
// B (Wh slice) resident: [32 n][1032 k] bf16 per half (pad 8 -> 2064B rows)
constexpr int B_ROW_BYTES = 1032 * 2;                  // 2064
constexpr int SM_BHI = 0;
constexpr int SM_BLO = SM_BHI + 32 * B_ROW_BYTES;      // 66048
// A chunks: [64 rows][136 k] bf16 (pad 8 -> 272B rows), double buffered, hi+lo
constexpr int A_ROW_BYTES = 136 * 2;                   // 272
constexpr int A_BUF = 64 * A_ROW_BYTES;                // 17408
constexpr int SM_A_HI = SM_BLO + 32 * B_ROW_BYTES;     // 132096
constexpr int SM_A_LO = SM_A_HI + 2 * A_BUF;           // 166912
constexpr int SM_RED = SM_A_HI;                        // reuse buf0-hi for k-reduction
constexpr int SMEM_P2 = SM_A_LO + 2 * A_BUF;           // 201728

// ---------------------------------------------------------------------------
// PTX helpers (baseline sm_103-legal: ldmatrix + mma.sync HMMA path)
// ---------------------------------------------------------------------------
__device__ __forceinline__ uint32_t smem_to_u32(const void* p) {
    uint32_t a;
    asm("{ .reg .u64 t; cvta.to.shared.u64 t, %1; cvt.u32.u64 %0, t; }"
        : "=r"(a) : "l"(p));
    return a;
}
__device__ __forceinline__ void ldsm4(uint32_t r[4], uint32_t addr) {
    asm volatile("ldmatrix.sync.aligned.m8n8.x4.shared.b16 {%0,%1,%2,%3}, [%4];"
                 : "=r"(r[0]), "=r"(r[1]), "=r"(r[2]), "=r"(r[3]) : "r"(addr));
}
// NOTE: NOT volatile — pure dataflow. Lets the compiler interleave MMAs
// across accumulator chains and hoist them between ldsm/LDG for latency hiding.
__device__ __forceinline__ void mma_bf16(float d[4], const uint32_t a[4],
                                         const uint32_t b[2]) {
    asm("mma.sync.aligned.m16n8k16.row.col.f32.bf16.bf16.f32 "
        "{%0,%1,%2,%3}, {%4,%5,%6,%7}, {%8,%9}, {%0,%1,%2,%3};"
        : "+f"(d[0]), "+f"(d[1]), "+f"(d[2]), "+f"(d[3])
        : "r"(a[0]), "r"(a[1]), "r"(a[2]), "r"(a[3]), "r"(b[0]), "r"(b[1]));
}

// ---------------------------------------------------------------------------
// Packed f32x2 helpers (phase-1 GEMM)
// ---------------------------------------------------------------------------
__device__ __forceinline__ unsigned long long pack2(float lo, float hi) {
    unsigned long long r;
    asm("mov.b64 %0, {%1, %2};" : "=l"(r) : "f"(lo), "f"(hi));
    return r;
}
__device__ __forceinline__ unsigned long long ffma2(unsigned long long a,
                                                    unsigned long long b,
                                                    unsigned long long c) {
    unsigned long long d;
    asm("fma.rn.f32x2 %0, %1, %2, %3;" : "=l"(d) : "l"(a), "l"(b), "l"(c));
    return d;
}
__device__ __forceinline__ float2 unpack2(unsigned long long v) {
    float2 f;
    asm("mov.b64 {%0, %1}, %2;" : "=f"(f.x), "=f"(f.y) : "l"(v));
    return f;
}

// ---------------------------------------------------------------------------
// Setup kernels
// ---------------------------------------------------------------------------
__global__ void reset_kernel() {
    if (threadIdx.x < T_DIM) g_cnt[threadIdx.x] = 0;
}

__global__ __launch_bounds__(256) void split_wh_kernel(const float* __restrict__ W) {
    int i = (blockIdx.x * 256 + threadIdx.x) * 4;
    float4 w = *reinterpret_cast<const float4*>(W + i);
#pragma unroll
    for (int j = 0; j < 4; j++) {
        float v = (&w.x)[j];
        __nv_bfloat16 hi = __float2bfloat16(v);
        float r = v - __bfloat162float(hi);
        g_Wh_hi[i + j] = hi;
        g_Wh_lo[i + j] = __float2bfloat16(r);
    }
}

__global__ __launch_bounds__(256) void split_h0_kernel(const float* __restrict__ h0) {
    int i = (blockIdx.x * 256 + threadIdx.x) * 4;
    float4 v4 = *reinterpret_cast<const float4*>(h0 + i);
#pragma unroll
    for (int j = 0; j < 4; j++) {
        float v = (&v4.x)[j];
        __nv_bfloat16 hi = __float2bfloat16(v);
        float r = v - __bfloat162float(hi);
        g_h_hi[0][i + j] = hi;
        g_h_lo[0][i + j] = __float2bfloat16(r);
    }
}

// ---------------------------------------------------------------------------
// Phase 1: xi = x @ Wi^T + bi (FFMA2 SGEMM, unchanged - proven)
// ---------------------------------------------------------------------------
__global__ __launch_bounds__(256) void gemm_xi_kernel(
    const float* __restrict__ A, const float* __restrict__ Bw,
    const float* __restrict__ bias, float* __restrict__ C)
{
    __shared__ float As[8][128];
    __shared__ float Bs[8][128];

    const int tid = threadIdx.x;
    const int m0 = blockIdx.y * 128;
    const int n0 = blockIdx.x * 128;
    const int tx = tid & 15;
    const int ty = tid >> 4;
    const int lr = tid >> 1;
    const int lc = (tid & 1) * 4;

    unsigned long long acc[8][4];
#pragma unroll
    for (int i = 0; i < 8; i++)
#pragma unroll
        for (int j = 0; j < 4; j++) acc[i][j] = 0ull;

    const float* aLoad = A + (size_t)(m0 + lr) * IN_DIM + lc;
    const float* bLoad = Bw + (size_t)(n0 + lr) * IN_DIM + lc;

    for (int k0 = 0; k0 < IN_DIM; k0 += 8) {
        float4 av = *reinterpret_cast<const float4*>(aLoad + k0);
        float4 bv = *reinterpret_cast<const float4*>(bLoad + k0);
        As[lc + 0][lr] = av.x; As[lc + 1][lr] = av.y;
        As[lc + 2][lr] = av.z; As[lc + 3][lr] = av.w;
        Bs[lc + 0][lr] = bv.x; Bs[lc + 1][lr] = bv.y;
        Bs[lc + 2][lr] = bv.z; Bs[lc + 3][lr] = bv.w;
        __syncthreads();

#pragma unroll
        for (int k = 0; k < 8; k++) {
            float4 a0 = *reinterpret_cast<const float4*>(&As[k][ty * 8]);
            float4 a1 = *reinterpret_cast<const float4*>(&As[k][ty * 8 + 4]);
            ulonglong2 b01 = *reinterpret_cast<const ulonglong2*>(&Bs[k][tx * 8]);
            ulonglong2 b23 = *reinterpret_cast<const ulonglong2*>(&Bs[k][tx * 8 + 4]);
            float a[8] = {a0.x, a0.y, a0.z, a0.w, a1.x, a1.y, a1.z, a1.w};
#pragma unroll
            for (int i = 0; i < 8; i++) {
                unsigned long long a2 = pack2(a[i], a[i]);
                acc[i][0] = ffma2(a2, b01.x, acc[i][0]);
                acc[i][1] = ffma2(a2, b01.y, acc[i][1]);
                acc[i][2] = ffma2(a2, b23.x, acc[i][2]);
                acc[i][3] = ffma2(a2, b23.y, acc[i][3]);
            }
        }
        __syncthreads();
    }

    float bb[8];
#pragma unroll
    for (int j = 0; j < 8; j++) bb[j] = bias[n0 + tx * 8 + j];

#pragma unroll
    for (int i = 0; i < 8; i++) {
        float c[8];
#pragma unroll
        for (int j = 0; j < 4; j++) {
            float2 v = unpack2(acc[i][j]);
            c[2 * j + 0] = v.x + bb[2 * j + 0];
            c[2 * j + 1] = v.y + bb[2 * j + 1];
        }
        float* cp = C + (size_t)(m0 + ty * 8 + i) * H_DIM + n0 + tx * 8;
        *reinterpret_cast<float4*>(cp + 0) = make_float4(c[0], c[1], c[2], c[3]);
        *reinterpret_cast<float4*>(cp + 4) = make_float4(c[4], c[5], c[6], c[7]);
    }
}

// ---------------------------------------------------------------------------
// Phase 2: persistent HMMA recurrence (mma.sync m16n8k16 bf16, bf16x3 split).
// 128 CTAs (32 n-tiles x 4 m-tiles of 64x32), 256 threads (8 warps).
// Changes vs R7: (1) mma asm non-volatile + term-major ordering -> 4-chain ILP
// instead of 3 back-to-back RAW MMAs on one accumulator; (2) epilogue spread
// across all 8 warps (each kh-half publishes the opposite rp's partials into
// disjoint RED rows, then reduces + tanh's its own rp).
// ---------------------------------------------------------------------------
__global__ __launch_bounds__(256, 1) void rnn_hmma(
    const float* __restrict__ bh, float* __restrict__ out)
{
    extern __shared__ char sm[];
    const uint32_t sb = smem_to_u32(sm);
    const int tid = threadIdx.x;
    const int wid = tid >> 5;
    const int lane = tid & 31;
    const int n0 = blockIdx.x * 32;
    const int m0 = blockIdx.y * 64;
    const int mt = wid & 3;     // m16 tile
    const int kh = wid >> 2;    // k-half within chunk
    const int g = lane >> 2;
    const int tig = lane & 3;

    // One-time: load resident Wh hi/lo slice [32n][1024k] into padded smem.
    for (int i = 0; i < 16; i++) {
        int u = tid + 256 * i;               // 0..4095 uint4 units per half
        int n = u >> 7;                      // 0..31
        int kq = (u & 127) * 8;              // 0..1016
        uint4 vh = *reinterpret_cast<const uint4*>(&g_Wh_hi[(size_t)(n0 + n) * H_DIM + kq]);
        uint4 vl = *reinterpret_cast<const uint4*>(&g_Wh_lo[(size_t)(n0 + n) * H_DIM + kq]);
        *reinterpret_cast<uint4*>(sm + SM_BHI + n * B_ROW_BYTES + kq * 2) = vh;
        *reinterpret_cast<uint4*>(sm + SM_BLO + n * B_ROW_BYTES + kq * 2) = vl;
    }
    __syncthreads();

    // ldmatrix lane-address components (proven R7 mappings).
    const uint32_t aByte =
        (uint32_t)((mt * 16 + (lane & 7) + ((lane >> 3) & 1) * 8) * A_ROW_BYTES
                   + ((lane >> 4) & 1) * 16);
    const uint32_t bRow = (uint32_t)((lane & 7) + ((lane >> 4) & 1) * 8);
    const uint32_t bKof = ((lane >> 3) & 1) * 16;
    const uint32_t bByte0 = bRow * B_ROW_BYTES + bKof;
    const uint32_t bByte1 = (bRow + 16) * B_ROW_BYTES + bKof;

    float2 bb[4];
#pragma unroll
    for (int nt = 0; nt < 4; nt++)
        bb[nt] = *reinterpret_cast<const float2*>(&bh[n0 + nt * 8 + tig * 2]);

    for (int t = 0; t < T_DIM; t++) {
        const int pb = t & 1;
        const __nv_bfloat16* Ah = g_h_hi[pb] + (size_t)m0 * H_DIM;
        const __nv_bfloat16* Al = g_h_lo[pb] + (size_t)m0 * H_DIM;

        float d[4][4];
#pragma unroll
        for (int nt = 0; nt < 4; nt++)
#pragma unroll
            for (int e = 0; e < 4; e++) d[nt][e] = 0.0f;

        // Prefetch chunk 0 (A [64 rows][128 k] hi+lo, coalesced uint4)
        uint4 rh[4], rl[4];
#pragma unroll
        for (int i = 0; i < 4; i++) {
            int u = tid + 256 * i;           // 0..1023
            int row = u >> 4;                // 0..63
            int kq = (u & 15) * 8;           // 0..120
            rh[i] = *reinterpret_cast<const uint4*>(&Ah[(size_t)row * H_DIM + kq]);
            rl[i] = *reinterpret_cast<const uint4*>(&Al[(size_t)row * H_DIM + kq]);
        }

        for (int kc = 0; kc < 8; kc++) {
            const int buf = kc & 1;
            char* ah_s = sm + SM_A_HI + buf * A_BUF;
            char* al_s = sm + SM_A_LO + buf * A_BUF;
            // STS (conflict-free: contiguous 16B within padded rows)
#pragma unroll
            for (int i = 0; i < 4; i++) {
                int u = tid + 256 * i;
                int row = u >> 4;
                int kq = (u & 15) * 8;
                *reinterpret_cast<uint4*>(ah_s + row * A_ROW_BYTES + kq * 2) = rh[i];
                *reinterpret_cast<uint4*>(al_s + row * A_ROW_BYTES + kq * 2) = rl[i];
            }
            __syncthreads();
            // Prefetch next chunk (latency hidden by the mma work below)
            if (kc + 1 < 8) {
                const int kb = (kc + 1) * 128;
#pragma unroll
                for (int i = 0; i < 4; i++) {
                    int u = tid + 256 * i;
                    int row = u >> 4;
                    int kq = (u & 15) * 8;
                    rh[i] = *reinterpret_cast<const uint4*>(&Ah[(size_t)row * H_DIM + kb + kq]);
                    rl[i] = *reinterpret_cast<const uint4*>(&Al[(size_t)row * H_DIM + kb + kq]);
                }
            }
            // Compute this chunk: 4 k16 steps on this warp's k-half.
            // Term-major MMA order: same-accumulator issue distance = 4.
            const uint32_t ahB = sb + SM_A_HI + buf * A_BUF + aByte + kh * 128;
            const uint32_t alB = sb + SM_A_LO + buf * A_BUF + aByte + kh * 128;
            const uint32_t bkB = (uint32_t)((kc * 128 + kh * 64) * 2);
#pragma unroll
            for (int ks = 0; ks < 4; ks++) {
                uint32_t a_hi[4], a_lo[4], b_h[8], b_l[8];
                ldsm4(a_hi, ahB + ks * 32);
                ldsm4(a_lo, alB + ks * 32);
                ldsm4(b_h,     sb + SM_BHI + bByte0 + bkB + ks * 32);
                ldsm4(b_h + 4, sb + SM_BHI + bByte1 + bkB + ks * 32);
                ldsm4(b_l,     sb + SM_BLO + bByte0 + bkB + ks * 32);
                ldsm4(b_l + 4, sb + SM_BLO + bByte1 + bkB + ks * 32);
#pragma unroll
                for (int nt = 0; nt < 4; nt++)
                    mma_bf16(d[nt], a_hi, &b_h[(nt >> 1) * 4 + (nt & 1) * 2]);
#pragma unroll
                for (int nt = 0; nt < 4; nt++)
                    mma_bf16(d[nt], a_lo, &b_h[(nt >> 1) * 4 + (nt & 1) * 2]);
#pragma unroll
                for (int nt = 0; nt < 4; nt++)
                    mma_bf16(d[nt], a_hi, &b_l[(nt >> 1) * 4 + (nt & 1) * 2]);
            }
        }
        __syncthreads();

        // Cross-warp k-reduction, spread across all warps:
        // kh=0 publishes its rp=1 rows (g+8); kh=1 publishes rp=0 rows (g).
        {
            const int prow = mt * 16 + g + (kh == 0 ? 8 : 0);
            const int rpPub = (kh == 0) ? 1 : 0;
#pragma unroll
            for (int nt = 0; nt < 4; nt++)
                *reinterpret_cast<float2*>(
                    sm + SM_RED + prow * 136 + (nt * 8 + tig * 2) * 4) =
                    make_float2(d[nt][rpPub * 2], d[nt][rpPub * 2 + 1]);
        }
        __syncthreads();

        // Each half reduces + epilogues its own rp (kh=0 -> rp0, kh=1 -> rp1).
        {
            const int rp = kh;
            const int pb1 = pb ^ 1;
            const int lrow = mt * 16 + g + 8 * kh;
            const int row = m0 + lrow;
            float* outT = out + (size_t)t * BH;
#pragma unroll
            for (int nt = 0; nt < 4; nt++) {
                const int col = n0 + nt * 8 + tig * 2;
                float2 p = *reinterpret_cast<const float2*>(
                    sm + SM_RED + lrow * 136 + (nt * 8 + tig * 2) * 4);
                float sx = d[nt][rp * 2] + p.x;
                float sy = d[nt][rp * 2 + 1] + p.y;
                float* op = outT + (size_t)row * H_DIM + col;
                float2 xv = *reinterpret_cast<const float2*>(op);
                float ox = tanhf(sx + xv.x + bb[nt].x);
                float oy = tanhf(sy + xv.y + bb[nt].y);
                *reinterpret_cast<float2*>(op) = make_float2(ox, oy);
                __nv_bfloat16 hx = __float2bfloat16(ox);
                __nv_bfloat16 hy = __float2bfloat16(oy);
                __nv_bfloat162 hv; hv.x = hx; hv.y = hy;
                *reinterpret_cast<__nv_bfloat162*>(
                    &g_h_hi[pb1][(size_t)row * H_DIM + col]) = hv;
                __nv_bfloat162 lv;
                lv.x = __float2bfloat16(ox - __bfloat162float(hx));
                lv.y = __float2bfloat16(oy - __bfloat162float(hy));
                *reinterpret_cast<__nv_bfloat162*>(
                    &g_h_lo[pb1][(size_t)row * H_DIM + col]) = lv;
            }
        }

        // Device-wide step barrier
        if (t + 1 < T_DIM) {
            __syncthreads();
            __threadfence();
            if (tid == 0) {
                atomicAdd(&g_cnt[t], 1);
                volatile int* p = &g_cnt[t];
                while (*p < N_CTAS) { }
            }
            __syncthreads();
            __threadfence();
        }
    }
}

// ---------------------------------------------------------------------------
// Launch
// inputs: 0=x [T,B,IN], 1=h [B,H], 2=Wi_w [H,IN], 3=Wi_b [H],
//         4=Wh_w [H,H], 5=Wh_b [H];  output: hiddens [T,B,H]
// ---------------------------------------------------------------------------
extern "C" void kernel_launch(void* const* d_in, const int* in_sizes, int n_in,
                              void* d_out, int out_size) {
    const float* x   = (const float*)d_in[0];
    const float* h0  = (const float*)d_in[1];
    const float* Wi  = (const float*)d_in[2];
    const float* bi  = (const float*)d_in[3];
    const float* Wh  = (const float*)d_in[4];
    const float* bh  = (const float*)d_in[5];
    float* out = (float*)d_out;

    static bool attr_set = false;
    if (!attr_set) {
        cudaFuncSetAttribute(rnn_hmma,
                             cudaFuncAttributeMaxDynamicSharedMemorySize,
                             SMEM_P2);
        attr_set = true;
    }

    reset_kernel<<<1, 256>>>();
    split_wh_kernel<<<H_DIM * H_DIM / 1024, 256>>>(Wh);
    split_h0_kernel<<<BH / 1024, 256>>>(h0);

    // Phase 1: xi for all timesteps, written straight into d_out
    gemm_xi_kernel<<<dim3(H_DIM / 128, M1 / 128), 256>>>(x, Wi, bi, out);

    // Phase 2: persistent HMMA recurrence (Wh resident in smem)
    rnn_hmma<<<dim3(32, 4), 256, SMEM_P2>>>(bh, out);
}

// round 11
// speedup vs baseline: 1.0416x; 1.0416x over previous
#include <cuda_runtime.h>
#include <cuda_bf16.h>
#include <cstdint>

// Problem constants
constexpr int T_DIM = 256;
constexpr int B_DIM = 256;
constexpr int IN_DIM = 1024;
constexpr int H_DIM = 1024;
constexpr int M1 = T_DIM * B_DIM;
constexpr int BH = B_DIM * H_DIM;

// ---------------------------------------------------------------------------
// Device globals (static allocations - allowed)
// ---------------------------------------------------------------------------
__device__ int g_cnt[T_DIM];                       // per-step barrier counters
__device__ __nv_bfloat16 g_Wh_hi[H_DIM * H_DIM];   // Wh split hi
__device__ __nv_bfloat16 g_Wh_lo[H_DIM * H_DIM];   // Wh split lo
__device__ __nv_bfloat16 g_h_hi[2][BH];            // h split hi (step parity)
__device__ __nv_bfloat16 g_h_lo[2][BH];            // h split lo

constexpr int N_CTAS = 128;    // GLOBAL barrier (proven R3-R8)

// Shared memory layout (bytes) for the persistent kernel
// B (Wh slice) resident: [32 n][1032 k] bf16 per half (pad 8 -> 2064B rows)
constexpr int B_ROW_BYTES = 1032 * 2;                  // 2064
constexpr int SM_BHI = 0;
constexpr int SM_BLO = SM_BHI + 32 * B_ROW_BYTES;      // 66048
// A chunks: [64 rows][136 k] bf16 (pad 8 -> 272B rows), double buffered, hi+lo
constexpr int A_ROW_BYTES = 136 * 2;                   // 272
constexpr int A_BUF = 64 * A_ROW_BYTES;                // 17408
constexpr int SM_A_HI = SM_BLO + 32 * B_ROW_BYTES;     // 132096
constexpr int SM_A_LO = SM_A_HI + 2 * A_BUF;           // 166912
constexpr int SM_RED = SM_A_HI;                        // reuse buf0-hi for k-reduction
constexpr int SMEM_P2 = SM_A_LO + 2 * A_BUF;           // 201728

// ---------------------------------------------------------------------------
// PTX helpers (baseline sm_103-legal: ldmatrix + mma.sync HMMA path)
// ---------------------------------------------------------------------------
__device__ __forceinline__ uint32_t smem_to_u32(const void* p) {
    uint32_t a;
    asm("{ .reg .u64 t; cvta.to.shared.u64 t, %1; cvt.u32.u64 %0, t; }"
        : "=r"(a) : "l"(p));
    return a;
}
__device__ __forceinline__ void ldsm4(uint32_t r[4], uint32_t addr) {
    asm volatile("ldmatrix.sync.aligned.m8n8.x4.shared.b16 {%0,%1,%2,%3}, [%4];"
                 : "=r"(r[0]), "=r"(r[1]), "=r"(r[2]), "=r"(r[3]) : "r"(addr));
}
__device__ __forceinline__ void mma_bf16(float d[4], const uint32_t a[4],
                                         const uint32_t b[2]) {
    asm("mma.sync.aligned.m16n8k16.row.col.f32.bf16.bf16.f32 "
        "{%0,%1,%2,%3}, {%4,%5,%6,%7}, {%8,%9}, {%0,%1,%2,%3};"
        : "+f"(d[0]), "+f"(d[1]), "+f"(d[2]), "+f"(d[3])
        : "r"(a[0]), "r"(a[1]), "r"(a[2]), "r"(a[3]), "r"(b[0]), "r"(b[1]));
}

// ---------------------------------------------------------------------------
// Packed f32x2 helpers (phase-1 GEMM)
// ---------------------------------------------------------------------------
__device__ __forceinline__ unsigned long long pack2(float lo, float hi) {
    unsigned long long r;
    asm("mov.b64 %0, {%1, %2};" : "=l"(r) : "f"(lo), "f"(hi));
    return r;
}
__device__ __forceinline__ unsigned long long ffma2(unsigned long long a,
                                                    unsigned long long b,
                                                    unsigned long long c) {
    unsigned long long d;
    asm("fma.rn.f32x2 %0, %1, %2, %3;" : "=l"(d) : "l"(a), "l"(b), "l"(c));
    return d;
}
__device__ __forceinline__ float2 unpack2(unsigned long long v) {
    float2 f;
    asm("mov.b64 {%0, %1}, %2;" : "=f"(f.x), "=f"(f.y) : "l"(v));
    return f;
}

// ---------------------------------------------------------------------------
// Setup kernels.
// reset: zero the 256 step counters.
// split_all: blocks 0..1023 split Wh (H*H elems); blocks 1024..1279 split h0
//            (BH elems -- 256 blocks, FIXED: R9/R10 launched only 64, leaving
//            stale g_h rows 64..255 on replay -> deterministic divergence).
// ---------------------------------------------------------------------------
__global__ void reset_kernel() {
    if (threadIdx.x < T_DIM) g_cnt[threadIdx.x] = 0;
}

constexpr int SPLIT_WH_BLOCKS = (H_DIM * H_DIM) / 1024;  // 1024
constexpr int SPLIT_H0_BLOCKS = BH / 1024;               // 256

__global__ __launch_bounds__(256) void split_all_kernel(
    const float* __restrict__ W, const float* __restrict__ h0)
{
    const int b = blockIdx.x;
    if (b < SPLIT_WH_BLOCKS) {
        int i = (b * 256 + threadIdx.x) * 4;
        float4 w = *reinterpret_cast<const float4*>(W + i);
#pragma unroll
        for (int j = 0; j < 4; j++) {
            float v = (&w.x)[j];
            __nv_bfloat16 hi = __float2bfloat16(v);
            g_Wh_hi[i + j] = hi;
            g_Wh_lo[i + j] = __float2bfloat16(v - __bfloat162float(hi));
        }
    } else {
        int i = ((b - SPLIT_WH_BLOCKS) * 256 + threadIdx.x) * 4;
        float4 v4 = *reinterpret_cast<const float4*>(h0 + i);
#pragma unroll
        for (int j = 0; j < 4; j++) {
            float v = (&v4.x)[j];
            __nv_bfloat16 hi = __float2bfloat16(v);
            g_h_hi[0][i + j] = hi;
            g_h_lo[0][i + j] = __float2bfloat16(v - __bfloat162float(hi));
        }
    }
}

// ---------------------------------------------------------------------------
// Phase 1: xi = x @ Wi^T + (bi + bh)  (FFMA2 SGEMM; bh folded into the bias
// so the recurrence epilogue computes just tanh(D + xi)).
// ---------------------------------------------------------------------------
__global__ __launch_bounds__(256) void gemm_xi_kernel(
    const float* __restrict__ A, const float* __restrict__ Bw,
    const float* __restrict__ bias, const float* __restrict__ bias2,
    float* __restrict__ C)
{
    __shared__ float As[8][128];
    __shared__ float Bs[8][128];

    const int tid = threadIdx.x;
    const int m0 = blockIdx.y * 128;
    const int n0 = blockIdx.x * 128;
    const int tx = tid & 15;
    const int ty = tid >> 4;
    const int lr = tid >> 1;
    const int lc = (tid & 1) * 4;

    unsigned long long acc[8][4];
#pragma unroll
    for (int i = 0; i < 8; i++)
#pragma unroll
        for (int j = 0; j < 4; j++) acc[i][j] = 0ull;

    const float* aLoad = A + (size_t)(m0 + lr) * IN_DIM + lc;
    const float* bLoad = Bw + (size_t)(n0 + lr) * IN_DIM + lc;

    for (int k0 = 0; k0 < IN_DIM; k0 += 8) {
        float4 av = *reinterpret_cast<const float4*>(aLoad + k0);
        float4 bv = *reinterpret_cast<const float4*>(bLoad + k0);
        As[lc + 0][lr] = av.x; As[lc + 1][lr] = av.y;
        As[lc + 2][lr] = av.z; As[lc + 3][lr] = av.w;
        Bs[lc + 0][lr] = bv.x; Bs[lc + 1][lr] = bv.y;
        Bs[lc + 2][lr] = bv.z; Bs[lc + 3][lr] = bv.w;
        __syncthreads();

#pragma unroll
        for (int k = 0; k < 8; k++) {
            float4 a0 = *reinterpret_cast<const float4*>(&As[k][ty * 8]);
            float4 a1 = *reinterpret_cast<const float4*>(&As[k][ty * 8 + 4]);
            ulonglong2 b01 = *reinterpret_cast<const ulonglong2*>(&Bs[k][tx * 8]);
            ulonglong2 b23 = *reinterpret_cast<const ulonglong2*>(&Bs[k][tx * 8 + 4]);
            float a[8] = {a0.x, a0.y, a0.z, a0.w, a1.x, a1.y, a1.z, a1.w};
#pragma unroll
            for (int i = 0; i < 8; i++) {
                unsigned long long a2 = pack2(a[i], a[i]);
                acc[i][0] = ffma2(a2, b01.x, acc[i][0]);
                acc[i][1] = ffma2(a2, b01.y, acc[i][1]);
                acc[i][2] = ffma2(a2, b23.x, acc[i][2]);
                acc[i][3] = ffma2(a2, b23.y, acc[i][3]);
            }
        }
        __syncthreads();
    }

    float bb[8];
#pragma unroll
    for (int j = 0; j < 8; j++)
        bb[j] = bias[n0 + tx * 8 + j] + bias2[n0 + tx * 8 + j];

#pragma unroll
    for (int i = 0; i < 8; i++) {
        float c[8];
#pragma unroll
        for (int j = 0; j < 4; j++) {
            float2 v = unpack2(acc[i][j]);
            c[2 * j + 0] = v.x + bb[2 * j + 0];
            c[2 * j + 1] = v.y + bb[2 * j + 1];
        }
        float* cp = C + (size_t)(m0 + ty * 8 + i) * H_DIM + n0 + tx * 8;
        *reinterpret_cast<float4*>(cp + 0) = make_float4(c[0], c[1], c[2], c[3]);
        *reinterpret_cast<float4*>(cp + 4) = make_float4(c[4], c[5], c[6], c[7]);
    }
}

// ---------------------------------------------------------------------------
// Phase 2: persistent HMMA recurrence (mma.sync m16n8k16 bf16, bf16x3 split).
// 128 CTAs (32 n-tiles x 4 m-tiles of 64x32), 256 threads (8 warps).
// GLOBAL 128-CTA step barrier. Hoisted xi loads; bh folded into xi.
// ---------------------------------------------------------------------------
__global__ __launch_bounds__(256, 1) void rnn_hmma(
    float* __restrict__ out)
{
    extern __shared__ char sm[];
    const uint32_t sb = smem_to_u32(sm);
    const int tid = threadIdx.x;
    const int wid = tid >> 5;
    const int lane = tid & 31;
    const int n0 = blockIdx.x * 32;
    const int m0 = blockIdx.y * 64;
    const int mt = wid & 3;     // m16 tile
    const int kh = wid >> 2;    // k-half within chunk
    const int g = lane >> 2;
    const int tig = lane & 3;

    // One-time: load resident Wh hi/lo slice [32n][1024k] into padded smem.
    for (int i = 0; i < 16; i++) {
        int u = tid + 256 * i;               // 0..4095 uint4 units per half
        int n = u >> 7;                      // 0..31
        int kq = (u & 127) * 8;              // 0..1016
        uint4 vh = *reinterpret_cast<const uint4*>(&g_Wh_hi[(size_t)(n0 + n) * H_DIM + kq]);
        uint4 vl = *reinterpret_cast<const uint4*>(&g_Wh_lo[(size_t)(n0 + n) * H_DIM + kq]);
        *reinterpret_cast<uint4*>(sm + SM_BHI + n * B_ROW_BYTES + kq * 2) = vh;
        *reinterpret_cast<uint4*>(sm + SM_BLO + n * B_ROW_BYTES + kq * 2) = vl;
    }
    __syncthreads();

    // ldmatrix lane-address components (proven mappings).
    const uint32_t aByte =
        (uint32_t)((mt * 16 + (lane & 7) + ((lane >> 3) & 1) * 8) * A_ROW_BYTES
                   + ((lane >> 4) & 1) * 16);
    const uint32_t bRow = (uint32_t)((lane & 7) + ((lane >> 4) & 1) * 8);
    const uint32_t bKof = ((lane >> 3) & 1) * 16;
    const uint32_t bByte0 = bRow * B_ROW_BYTES + bKof;
    const uint32_t bByte1 = (bRow + 16) * B_ROW_BYTES + bKof;

    // Per-thread epilogue coordinates (constant across steps).
    const int lrow = mt * 16 + g + 8 * kh;
    const int row = m0 + lrow;

    for (int t = 0; t < T_DIM; t++) {
        const int pb = t & 1;
        const __nv_bfloat16* Ah = g_h_hi[pb] + (size_t)m0 * H_DIM;
        const __nv_bfloat16* Al = g_h_lo[pb] + (size_t)m0 * H_DIM;

        // Hoisted xi loads (DRAM latency hides under the whole kc loop).
        float* outT = out + (size_t)t * BH;
        float2 xv[4];
#pragma unroll
        for (int nt = 0; nt < 4; nt++)
            xv[nt] = __ldcg(reinterpret_cast<const float2*>(
                &outT[(size_t)row * H_DIM + n0 + nt * 8 + tig * 2]));

        float d[4][4];
#pragma unroll
        for (int nt = 0; nt < 4; nt++)
#pragma unroll
            for (int e = 0; e < 4; e++) d[nt][e] = 0.0f;

        // Prefetch chunk 0 (A [64 rows][128 k] hi+lo, coalesced uint4)
        uint4 rh[4], rl[4];
#pragma unroll
        for (int i = 0; i < 4; i++) {
            int u = tid + 256 * i;           // 0..1023
            int rrow = u >> 4;               // 0..63
            int kq = (u & 15) * 8;           // 0..120
            rh[i] = *reinterpret_cast<const uint4*>(&Ah[(size_t)rrow * H_DIM + kq]);
            rl[i] = *reinterpret_cast<const uint4*>(&Al[(size_t)rrow * H_DIM + kq]);
        }

        for (int kc = 0; kc < 8; kc++) {
            const int buf = kc & 1;
            char* ah_s = sm + SM_A_HI + buf * A_BUF;
            char* al_s = sm + SM_A_LO + buf * A_BUF;
            // STS (conflict-free: contiguous 16B within padded rows)
#pragma unroll
            for (int i = 0; i < 4; i++) {
                int u = tid + 256 * i;
                int rrow = u >> 4;
                int kq = (u & 15) * 8;
                *reinterpret_cast<uint4*>(ah_s + rrow * A_ROW_BYTES + kq * 2) = rh[i];
                *reinterpret_cast<uint4*>(al_s + rrow * A_ROW_BYTES + kq * 2) = rl[i];
            }
            __syncthreads();
            // Prefetch next chunk (latency hidden by the mma work below)
            if (kc + 1 < 8) {
                const int kb = (kc + 1) * 128;
#pragma unroll
                for (int i = 0; i < 4; i++) {
                    int u = tid + 256 * i;
                    int rrow = u >> 4;
                    int kq = (u & 15) * 8;
                    rh[i] = *reinterpret_cast<const uint4*>(&Ah[(size_t)rrow * H_DIM + kb + kq]);
                    rl[i] = *reinterpret_cast<const uint4*>(&Al[(size_t)rrow * H_DIM + kb + kq]);
                }
            }
            // Compute this chunk: 4 k16 steps on this warp's k-half.
            const uint32_t ahB = sb + SM_A_HI + buf * A_BUF + aByte + kh * 128;
            const uint32_t alB = sb + SM_A_LO + buf * A_BUF + aByte + kh * 128;
            const uint32_t bkB = (uint32_t)((kc * 128 + kh * 64) * 2);
#pragma unroll
            for (int ks = 0; ks < 4; ks++) {
                uint32_t a_hi[4], a_lo[4], b_h[8], b_l[8];
                ldsm4(a_hi, ahB + ks * 32);
                ldsm4(a_lo, alB + ks * 32);
                ldsm4(b_h,     sb + SM_BHI + bByte0 + bkB + ks * 32);
                ldsm4(b_h + 4, sb + SM_BHI + bByte1 + bkB + ks * 32);
                ldsm4(b_l,     sb + SM_BLO + bByte0 + bkB + ks * 32);
                ldsm4(b_l + 4, sb + SM_BLO + bByte1 + bkB + ks * 32);
#pragma unroll
                for (int nt = 0; nt < 4; nt++)
                    mma_bf16(d[nt], a_hi, &b_h[(nt >> 1) * 4 + (nt & 1) * 2]);
#pragma unroll
                for (int nt = 0; nt < 4; nt++)
                    mma_bf16(d[nt], a_lo, &b_h[(nt >> 1) * 4 + (nt & 1) * 2]);
#pragma unroll
                for (int nt = 0; nt < 4; nt++)
                    mma_bf16(d[nt], a_hi, &b_l[(nt >> 1) * 4 + (nt & 1) * 2]);
            }
        }
        __syncthreads();

        // Cross-warp k-reduction, spread across all warps:
        // kh=0 publishes its rp=1 rows (g+8); kh=1 publishes rp=0 rows (g).
        {
            const int prow = mt * 16 + g + (kh == 0 ? 8 : 0);
            const int rpPub = (kh == 0) ? 1 : 0;
#pragma unroll
            for (int nt = 0; nt < 4; nt++)
                *reinterpret_cast<float2*>(
                    sm + SM_RED + prow * 136 + (nt * 8 + tig * 2) * 4) =
                    make_float2(d[nt][rpPub * 2], d[nt][rpPub * 2 + 1]);
        }
        __syncthreads();

        // Each half reduces + epilogues its own rp (kh=0 -> rp0, kh=1 -> rp1).
        {
            const int rp = kh;
            const int pb1 = pb ^ 1;
#pragma unroll
            for (int nt = 0; nt < 4; nt++) {
                const int col = n0 + nt * 8 + tig * 2;
                float2 p = *reinterpret_cast<const float2*>(
                    sm + SM_RED + lrow * 136 + (nt * 8 + tig * 2) * 4);
                float sx = d[nt][rp * 2] + p.x;
                float sy = d[nt][rp * 2 + 1] + p.y;
                float ox = tanhf(sx + xv[nt].x);
                float oy = tanhf(sy + xv[nt].y);
                *reinterpret_cast<float2*>(
                    &outT[(size_t)row * H_DIM + col]) = make_float2(ox, oy);
                __nv_bfloat16 hx = __float2bfloat16(ox);
                __nv_bfloat16 hy = __float2bfloat16(oy);
                __nv_bfloat162 hv; hv.x = hx; hv.y = hy;
                *reinterpret_cast<__nv_bfloat162*>(
                    &g_h_hi[pb1][(size_t)row * H_DIM + col]) = hv;
                __nv_bfloat162 lv;
                lv.x = __float2bfloat16(ox - __bfloat162float(hx));
                lv.y = __float2bfloat16(oy - __bfloat162float(hy));
                *reinterpret_cast<__nv_bfloat162*>(
                    &g_h_lo[pb1][(size_t)row * H_DIM + col]) = lv;
            }
        }

        // GLOBAL device-wide step barrier (proven)
        if (t + 1 < T_DIM) {
            __syncthreads();
            __threadfence();
            if (tid == 0) {
                atomicAdd(&g_cnt[t], 1);
                volatile int* p = &g_cnt[t];
                while (*p < N_CTAS) { }
            }
            __syncthreads();
            __threadfence();
        }
    }
}

// ---------------------------------------------------------------------------
// Launch
// inputs: 0=x [T,B,IN], 1=h [B,H], 2=Wi_w [H,IN], 3=Wi_b [H],
//         4=Wh_w [H,H], 5=Wh_b [H];  output: hiddens [T,B,H]
// ---------------------------------------------------------------------------
extern "C" void kernel_launch(void* const* d_in, const int* in_sizes, int n_in,
                              void* d_out, int out_size) {
    const float* x   = (const float*)d_in[0];
    const float* h0  = (const float*)d_in[1];
    const float* Wi  = (const float*)d_in[2];
    const float* bi  = (const float*)d_in[3];
    const float* Wh  = (const float*)d_in[4];
    const float* bh  = (const float*)d_in[5];
    float* out = (float*)d_out;

    static bool attr_set = false;
    if (!attr_set) {
        cudaFuncSetAttribute(rnn_hmma,
                             cudaFuncAttributeMaxDynamicSharedMemorySize,
                             SMEM_P2);
        attr_set = true;
    }

    // Launch slot 1: reset counters; slot 2: split Wh+h0 (FULL coverage);
    // slot 3: xi GEMM; slot 4: rnn_hmma (the ncu-profiled slot).
    reset_kernel<<<1, 256>>>();
    split_all_kernel<<<SPLIT_WH_BLOCKS + SPLIT_H0_BLOCKS, 256>>>(Wh, h0);
    gemm_xi_kernel<<<dim3(H_DIM / 128, M1 / 128), 256>>>(x, Wi, bi, bh, out);
    rnn_hmma<<<dim3(32, 4), 256, SMEM_P2>>>(out);
}

// round 13
// speedup vs baseline: 1.1068x; 1.0626x over previous
#include <cuda_runtime.h>
#include <cuda_bf16.h>
#include <cstdint>

// Problem constants
constexpr int T_DIM = 256;
constexpr int B_DIM = 256;
constexpr int IN_DIM = 1024;
constexpr int H_DIM = 1024;
constexpr int M1 = T_DIM * B_DIM;
constexpr int BH = B_DIM * H_DIM;

// ---------------------------------------------------------------------------
// Device globals (static allocations - allowed)
// ---------------------------------------------------------------------------
__device__ int g_cnt[T_DIM];                       // per-step barrier counters
__device__ __nv_bfloat16 g_Wh_hi[H_DIM * H_DIM];   // Wh split hi
__device__ __nv_bfloat16 g_Wh_lo[H_DIM * H_DIM];   // Wh split lo
__device__ __nv_bfloat16 g_h_hi[2][BH];            // h split hi (step parity)
__device__ __nv_bfloat16 g_h_lo[2][BH];            // h split lo

constexpr int N_CTAS = 128;    // GLOBAL barrier (proven R3-R8, R11)

// Shared memory layout (bytes) for the persistent kernel
// B (Wh slice) resident: [32 n][1032 k] bf16 per half (pad 8 -> 2064B rows)
constexpr int B_ROW_BYTES = 1032 * 2;                  // 2064
constexpr int SM_BHI = 0;
constexpr int SM_BLO = SM_BHI + 32 * B_ROW_BYTES;      // 66048
// A chunks: [64 rows][136 k] bf16 (pad 8 -> 272B rows), double buffered, hi+lo
constexpr int A_ROW_BYTES = 136 * 2;                   // 272
constexpr int A_BUF = 64 * A_ROW_BYTES;                // 17408
constexpr int SM_A_HI = SM_BLO + 32 * B_ROW_BYTES;     // 132096
constexpr int SM_A_LO = SM_A_HI + 2 * A_BUF;           // 166912
// 4-way k-reduction buffers. Stride 144B = 16-byte aligned (R12 used 132 ->
// misaligned float4 trap). Reuses the A staging region (all 4 A buffers are
// dead at reduction time; next staging is past the step barrier's sync).
constexpr int RED_ROW_BYTES = 36 * 4;                  // 144 (16-aligned)
constexpr int QBUF_BYTES = 64 * RED_ROW_BYTES;         // 9216
constexpr int SM_RED = SM_A_HI;                        // 4*9216=36864 <= 4*A_BUF
static_assert(4 * QBUF_BYTES <= 4 * A_BUF, "RED region fits in A staging");
constexpr int SMEM_P2 = SM_A_LO + 2 * A_BUF;           // 201728

// ---------------------------------------------------------------------------
// PTX helpers (baseline sm_103-legal: ldmatrix + mma.sync HMMA path)
// ---------------------------------------------------------------------------
__device__ __forceinline__ uint32_t smem_to_u32(const void* p) {
    uint32_t a;
    asm("{ .reg .u64 t; cvta.to.shared.u64 t, %1; cvt.u32.u64 %0, t; }"
        : "=r"(a) : "l"(p));
    return a;
}
__device__ __forceinline__ void ldsm4(uint32_t r[4], uint32_t addr) {
    asm volatile("ldmatrix.sync.aligned.m8n8.x4.shared.b16 {%0,%1,%2,%3}, [%4];"
                 : "=r"(r[0]), "=r"(r[1]), "=r"(r[2]), "=r"(r[3]) : "r"(addr));
}
__device__ __forceinline__ void mma_bf16(float d[4], const uint32_t a[4],
                                         const uint32_t b[2]) {
    asm("mma.sync.aligned.m16n8k16.row.col.f32.bf16.bf16.f32 "
        "{%0,%1,%2,%3}, {%4,%5,%6,%7}, {%8,%9}, {%0,%1,%2,%3};"
        : "+f"(d[0]), "+f"(d[1]), "+f"(d[2]), "+f"(d[3])
        : "r"(a[0]), "r"(a[1]), "r"(a[2]), "r"(a[3]), "r"(b[0]), "r"(b[1]));
}

// ---------------------------------------------------------------------------
// Packed f32x2 helpers (phase-1 GEMM)
// ---------------------------------------------------------------------------
__device__ __forceinline__ unsigned long long pack2(float lo, float hi) {
    unsigned long long r;
    asm("mov.b64 %0, {%1, %2};" : "=l"(r) : "f"(lo), "f"(hi));
    return r;
}
__device__ __forceinline__ unsigned long long ffma2(unsigned long long a,
                                                    unsigned long long b,
                                                    unsigned long long c) {
    unsigned long long d;
    asm("fma.rn.f32x2 %0, %1, %2, %3;" : "=l"(d) : "l"(a), "l"(b), "l"(c));
    return d;
}
__device__ __forceinline__ float2 unpack2(unsigned long long v) {
    float2 f;
    asm("mov.b64 {%0, %1}, %2;" : "=f"(f.x), "=f"(f.y) : "l"(v));
    return f;
}

// ---------------------------------------------------------------------------
// Setup kernels (full-coverage split, fixed in R11)
// ---------------------------------------------------------------------------
__global__ void reset_kernel() {
    if (threadIdx.x < T_DIM) g_cnt[threadIdx.x] = 0;
}

constexpr int SPLIT_WH_BLOCKS = (H_DIM * H_DIM) / 1024;  // 1024
constexpr int SPLIT_H0_BLOCKS = BH / 1024;               // 256

__global__ __launch_bounds__(256) void split_all_kernel(
    const float* __restrict__ W, const float* __restrict__ h0)
{
    const int b = blockIdx.x;
    if (b < SPLIT_WH_BLOCKS) {
        int i = (b * 256 + threadIdx.x) * 4;
        float4 w = *reinterpret_cast<const float4*>(W + i);
#pragma unroll
        for (int j = 0; j < 4; j++) {
            float v = (&w.x)[j];
            __nv_bfloat16 hi = __float2bfloat16(v);
            g_Wh_hi[i + j] = hi;
            g_Wh_lo[i + j] = __float2bfloat16(v - __bfloat162float(hi));
        }
    } else {
        int i = ((b - SPLIT_WH_BLOCKS) * 256 + threadIdx.x) * 4;
        float4 v4 = *reinterpret_cast<const float4*>(h0 + i);
#pragma unroll
        for (int j = 0; j < 4; j++) {
            float v = (&v4.x)[j];
            __nv_bfloat16 hi = __float2bfloat16(v);
            g_h_hi[0][i + j] = hi;
            g_h_lo[0][i + j] = __float2bfloat16(v - __bfloat162float(hi));
        }
    }
}

// ---------------------------------------------------------------------------
// Phase 1: xi = x @ Wi^T + (bi + bh)  (FFMA2 SGEMM; bh folded into the bias)
// ---------------------------------------------------------------------------
__global__ __launch_bounds__(256) void gemm_xi_kernel(
    const float* __restrict__ A, const float* __restrict__ Bw,
    const float* __restrict__ bias, const float* __restrict__ bias2,
    float* __restrict__ C)
{
    __shared__ float As[8][128];
    __shared__ float Bs[8][128];

    const int tid = threadIdx.x;
    const int m0 = blockIdx.y * 128;
    const int n0 = blockIdx.x * 128;
    const int tx = tid & 15;
    const int ty = tid >> 4;
    const int lr = tid >> 1;
    const int lc = (tid & 1) * 4;

    unsigned long long acc[8][4];
#pragma unroll
    for (int i = 0; i < 8; i++)
#pragma unroll
        for (int j = 0; j < 4; j++) acc[i][j] = 0ull;

    const float* aLoad = A + (size_t)(m0 + lr) * IN_DIM + lc;
    const float* bLoad = Bw + (size_t)(n0 + lr) * IN_DIM + lc;

    for (int k0 = 0; k0 < IN_DIM; k0 += 8) {
        float4 av = *reinterpret_cast<const float4*>(aLoad + k0);
        float4 bv = *reinterpret_cast<const float4*>(bLoad + k0);
        As[lc + 0][lr] = av.x; As[lc + 1][lr] = av.y;
        As[lc + 2][lr] = av.z; As[lc + 3][lr] = av.w;
        Bs[lc + 0][lr] = bv.x; Bs[lc + 1][lr] = bv.y;
        Bs[lc + 2][lr] = bv.z; Bs[lc + 3][lr] = bv.w;
        __syncthreads();

#pragma unroll
        for (int k = 0; k < 8; k++) {
            float4 a0 = *reinterpret_cast<const float4*>(&As[k][ty * 8]);
            float4 a1 = *reinterpret_cast<const float4*>(&As[k][ty * 8 + 4]);
            ulonglong2 b01 = *reinterpret_cast<const ulonglong2*>(&Bs[k][tx * 8]);
            ulonglong2 b23 = *reinterpret_cast<const ulonglong2*>(&Bs[k][tx * 8 + 4]);
            float a[8] = {a0.x, a0.y, a0.z, a0.w, a1.x, a1.y, a1.z, a1.w};
#pragma unroll
            for (int i = 0; i < 8; i++) {
                unsigned long long a2 = pack2(a[i], a[i]);
                acc[i][0] = ffma2(a2, b01.x, acc[i][0]);
                acc[i][1] = ffma2(a2, b01.y, acc[i][1]);
                acc[i][2] = ffma2(a2, b23.x, acc[i][2]);
                acc[i][3] = ffma2(a2, b23.y, acc[i][3]);
            }
        }
        __syncthreads();
    }

    float bb[8];
#pragma unroll
    for (int j = 0; j < 8; j++)
        bb[j] = bias[n0 + tx * 8 + j] + bias2[n0 + tx * 8 + j];

#pragma unroll
    for (int i = 0; i < 8; i++) {
        float c[8];
#pragma unroll
        for (int j = 0; j < 4; j++) {
            float2 v = unpack2(acc[i][j]);
            c[2 * j + 0] = v.x + bb[2 * j + 0];
            c[2 * j + 1] = v.y + bb[2 * j + 1];
        }
        float* cp = C + (size_t)(m0 + ty * 8 + i) * H_DIM + n0 + tx * 8;
        *reinterpret_cast<float4*>(cp + 0) = make_float4(c[0], c[1], c[2], c[3]);
        *reinterpret_cast<float4*>(cp + 4) = make_float4(c[4], c[5], c[6], c[7]);
    }
}

// ---------------------------------------------------------------------------
// Phase 2: persistent HMMA recurrence, m32xn32 warp tile, 4-way k split.
// 128 CTAs (32 n-tiles x 4 m-tiles of 64x32), 256 threads (8 warps).
// Warp w: m32 tile = w&1, k-quarter (32 k's per 128-k chunk) = w>>1.
// Per k16: 4 A ldsm + 4 B ldsm + 24 mma (ratio 0.33 vs 0.5 before) ->
// CTA LDSM per step 1536 -> 1024. 4-way k-reduction via 4 padded smem
// buffers (144B rows, 16-aligned); uniform 256-thread epilogue.
// ---------------------------------------------------------------------------
__global__ __launch_bounds__(256, 1) void rnn_hmma(
    float* __restrict__ out)
{
    extern __shared__ char sm[];
    const uint32_t sb = smem_to_u32(sm);
    const int tid = threadIdx.x;
    const int wid = tid >> 5;
    const int lane = tid & 31;
    const int n0 = blockIdx.x * 32;
    const int m0 = blockIdx.y * 64;
    const int mt2 = wid & 1;    // m32 tile (rows mt2*32 .. +32)
    const int kq = wid >> 1;    // k-quarter within each 128-k chunk
    const int g = lane >> 2;
    const int tig = lane & 3;

    // One-time: load resident Wh hi/lo slice [32n][1024k] into padded smem.
    for (int i = 0; i < 16; i++) {
        int u = tid + 256 * i;               // 0..4095 uint4 units per half
        int n = u >> 7;                      // 0..31
        int kqd = (u & 127) * 8;             // 0..1016
        uint4 vh = *reinterpret_cast<const uint4*>(&g_Wh_hi[(size_t)(n0 + n) * H_DIM + kqd]);
        uint4 vl = *reinterpret_cast<const uint4*>(&g_Wh_lo[(size_t)(n0 + n) * H_DIM + kqd]);
        *reinterpret_cast<uint4*>(sm + SM_BHI + n * B_ROW_BYTES + kqd * 2) = vh;
        *reinterpret_cast<uint4*>(sm + SM_BLO + n * B_ROW_BYTES + kqd * 2) = vl;
    }
    __syncthreads();

    // ldmatrix lane-address components (proven mappings, extended to 2 m16 tiles).
    const uint32_t aByte0 =
        (uint32_t)((mt2 * 32 + (lane & 7) + ((lane >> 3) & 1) * 8) * A_ROW_BYTES
                   + ((lane >> 4) & 1) * 16 + kq * 64);
    const uint32_t aByte1 = aByte0 + 16 * A_ROW_BYTES;
    const uint32_t bRow = (uint32_t)((lane & 7) + ((lane >> 4) & 1) * 8);
    const uint32_t bKof = ((lane >> 3) & 1) * 16;
    const uint32_t bByte0 = bRow * B_ROW_BYTES + bKof;
    const uint32_t bByte1 = (bRow + 16) * B_ROW_BYTES + bKof;

    // Uniform epilogue coordinates: 1 row x 8 cols per thread.
    const int er = tid >> 2;             // 0..63
    const int ec = (tid & 3) * 8;        // col offset 0,8,16,24
    const int erow = m0 + er;

    for (int t = 0; t < T_DIM; t++) {
        const int pb = t & 1;
        const __nv_bfloat16* Ah = g_h_hi[pb] + (size_t)m0 * H_DIM;
        const __nv_bfloat16* Al = g_h_lo[pb] + (size_t)m0 * H_DIM;

        // Hoisted xi loads (DRAM latency hides under the whole kc loop).
        float* outT = out + (size_t)t * BH;
        float* xp = &outT[(size_t)erow * H_DIM + n0 + ec];
        const float4 xv0 = __ldcg(reinterpret_cast<const float4*>(xp));
        const float4 xv1 = __ldcg(reinterpret_cast<const float4*>(xp + 4));

        float d[2][4][4];
#pragma unroll
        for (int t2 = 0; t2 < 2; t2++)
#pragma unroll
            for (int nt = 0; nt < 4; nt++)
#pragma unroll
                for (int e = 0; e < 4; e++) d[t2][nt][e] = 0.0f;

        // Prefetch chunk 0 (A [64 rows][128 k] hi+lo, coalesced uint4)
        uint4 rh[4], rl[4];
#pragma unroll
        for (int i = 0; i < 4; i++) {
            int u = tid + 256 * i;           // 0..1023
            int rrow = u >> 4;               // 0..63
            int kqd = (u & 15) * 8;          // 0..120
            rh[i] = *reinterpret_cast<const uint4*>(&Ah[(size_t)rrow * H_DIM + kqd]);
            rl[i] = *reinterpret_cast<const uint4*>(&Al[(size_t)rrow * H_DIM + kqd]);
        }

        for (int kc = 0; kc < 8; kc++) {
            const int buf = kc & 1;
            char* ah_s = sm + SM_A_HI + buf * A_BUF;
            char* al_s = sm + SM_A_LO + buf * A_BUF;
            // STS (conflict-free: contiguous 16B within padded rows)
#pragma unroll
            for (int i = 0; i < 4; i++) {
                int u = tid + 256 * i;
                int rrow = u >> 4;
                int kqd = (u & 15) * 8;
                *reinterpret_cast<uint4*>(ah_s + rrow * A_ROW_BYTES + kqd * 2) = rh[i];
                *reinterpret_cast<uint4*>(al_s + rrow * A_ROW_BYTES + kqd * 2) = rl[i];
            }
            __syncthreads();
            // Prefetch next chunk (latency hidden by the mma work below)
            if (kc + 1 < 8) {
                const int kb = (kc + 1) * 128;
#pragma unroll
                for (int i = 0; i < 4; i++) {
                    int u = tid + 256 * i;
                    int rrow = u >> 4;
                    int kqd = (u & 15) * 8;
                    rh[i] = *reinterpret_cast<const uint4*>(&Ah[(size_t)rrow * H_DIM + kb + kqd]);
                    rl[i] = *reinterpret_cast<const uint4*>(&Al[(size_t)rrow * H_DIM + kb + kqd]);
                }
            }
            // Compute this chunk: 2 k16 steps on this warp's k-quarter.
            const uint32_t ah0 = sb + SM_A_HI + buf * A_BUF + aByte0;
            const uint32_t ah1 = sb + SM_A_HI + buf * A_BUF + aByte1;
            const uint32_t al0 = sb + SM_A_LO + buf * A_BUF + aByte0;
            const uint32_t al1 = sb + SM_A_LO + buf * A_BUF + aByte1;
            const uint32_t bkB = (uint32_t)(kc * 256 + kq * 64);
#pragma unroll
            for (int ks = 0; ks < 2; ks++) {
                uint32_t a_hi0[4], a_hi1[4], a_lo0[4], a_lo1[4];
                uint32_t b_h[8], b_l[8];
                ldsm4(a_hi0, ah0 + ks * 32);
                ldsm4(a_hi1, ah1 + ks * 32);
                ldsm4(a_lo0, al0 + ks * 32);
                ldsm4(a_lo1, al1 + ks * 32);
                ldsm4(b_h,     sb + SM_BHI + bByte0 + bkB + ks * 32);
                ldsm4(b_h + 4, sb + SM_BHI + bByte1 + bkB + ks * 32);
                ldsm4(b_l,     sb + SM_BLO + bByte0 + bkB + ks * 32);
                ldsm4(b_l + 4, sb + SM_BLO + bByte1 + bkB + ks * 32);
                // Term-major: hi*hi (8), lo*hi (8), hi*lo (8)
#pragma unroll
                for (int nt = 0; nt < 4; nt++) {
                    const uint32_t* ph = &b_h[(nt >> 1) * 4 + (nt & 1) * 2];
                    mma_bf16(d[0][nt], a_hi0, ph);
                    mma_bf16(d[1][nt], a_hi1, ph);
                }
#pragma unroll
                for (int nt = 0; nt < 4; nt++) {
                    const uint32_t* ph = &b_h[(nt >> 1) * 4 + (nt & 1) * 2];
                    mma_bf16(d[0][nt], a_lo0, ph);
                    mma_bf16(d[1][nt], a_lo1, ph);
                }
#pragma unroll
                for (int nt = 0; nt < 4; nt++) {
                    const uint32_t* pl = &b_l[(nt >> 1) * 4 + (nt & 1) * 2];
                    mma_bf16(d[0][nt], a_hi0, pl);
                    mma_bf16(d[1][nt], a_hi1, pl);
                }
            }
        }
        __syncthreads();

        // Publish all 4 k-quarter partials to padded smem buffers (8B aligned).
#pragma unroll
        for (int t2 = 0; t2 < 2; t2++)
#pragma unroll
            for (int nt = 0; nt < 4; nt++)
#pragma unroll
                for (int rp = 0; rp < 2; rp++) {
                    const int prow = mt2 * 32 + t2 * 16 + g + rp * 8;
                    *reinterpret_cast<float2*>(
                        sm + SM_RED + kq * QBUF_BYTES + prow * RED_ROW_BYTES
                        + (nt * 8 + tig * 2) * 4) =
                        make_float2(d[t2][nt][rp * 2], d[t2][nt][rp * 2 + 1]);
                }
        __syncthreads();

        // Uniform reduce + epilogue: each thread 1 row x 8 cols (16B aligned).
        {
            const int pb1 = pb ^ 1;
            float4 sA = make_float4(0.f, 0.f, 0.f, 0.f);
            float4 sB = make_float4(0.f, 0.f, 0.f, 0.f);
#pragma unroll
            for (int q = 0; q < 4; q++) {
                const char* base = sm + SM_RED + q * QBUF_BYTES
                                 + er * RED_ROW_BYTES + ec * 4;
                float4 pA = *reinterpret_cast<const float4*>(base);
                float4 pB = *reinterpret_cast<const float4*>(base + 16);
                sA.x += pA.x; sA.y += pA.y; sA.z += pA.z; sA.w += pA.w;
                sB.x += pB.x; sB.y += pB.y; sB.z += pB.z; sB.w += pB.w;
            }
            float ov[8];
            ov[0] = tanhf(sA.x + xv0.x); ov[1] = tanhf(sA.y + xv0.y);
            ov[2] = tanhf(sA.z + xv0.z); ov[3] = tanhf(sA.w + xv0.w);
            ov[4] = tanhf(sB.x + xv1.x); ov[5] = tanhf(sB.y + xv1.y);
            ov[6] = tanhf(sB.z + xv1.z); ov[7] = tanhf(sB.w + xv1.w);

            *reinterpret_cast<float4*>(xp)     = make_float4(ov[0], ov[1], ov[2], ov[3]);
            *reinterpret_cast<float4*>(xp + 4) = make_float4(ov[4], ov[5], ov[6], ov[7]);

            unsigned short hh[8], ll[8];
#pragma unroll
            for (int e = 0; e < 8; e++) {
                __nv_bfloat16 hb = __float2bfloat16(ov[e]);
                __nv_bfloat16 lb = __float2bfloat16(ov[e] - __bfloat162float(hb));
                hh[e] = *reinterpret_cast<unsigned short*>(&hb);
                ll[e] = *reinterpret_cast<unsigned short*>(&lb);
            }
            const size_t hoff = (size_t)erow * H_DIM + n0 + ec;
            *reinterpret_cast<uint4*>(&g_h_hi[pb1][hoff]) =
                *reinterpret_cast<const uint4*>(hh);
            *reinterpret_cast<uint4*>(&g_h_lo[pb1][hoff]) =
                *reinterpret_cast<const uint4*>(ll);
        }

        // GLOBAL device-wide step barrier (proven)
        if (t + 1 < T_DIM) {
            __syncthreads();
            __threadfence();
            if (tid == 0) {
                atomicAdd(&g_cnt[t], 1);
                volatile int* p = &g_cnt[t];
                while (*p < N_CTAS) { }
            }
            __syncthreads();
            __threadfence();
        }
    }
}

// ---------------------------------------------------------------------------
// Launch
// inputs: 0=x [T,B,IN], 1=h [B,H], 2=Wi_w [H,IN], 3=Wi_b [H],
//         4=Wh_w [H,H], 5=Wh_b [H];  output: hiddens [T,B,H]
// ---------------------------------------------------------------------------
extern "C" void kernel_launch(void* const* d_in, const int* in_sizes, int n_in,
                              void* d_out, int out_size) {
    const float* x   = (const float*)d_in[0];
    const float* h0  = (const float*)d_in[1];
    const float* Wi  = (const float*)d_in[2];
    const float* bi  = (const float*)d_in[3];
    const float* Wh  = (const float*)d_in[4];
    const float* bh  = (const float*)d_in[5];
    float* out = (float*)d_out;

    static bool attr_set = false;
    if (!attr_set) {
        cudaFuncSetAttribute(rnn_hmma,
                             cudaFuncAttributeMaxDynamicSharedMemorySize,
                             SMEM_P2);
        attr_set = true;
    }

    // Launch slot 1: reset counters; slot 2: split Wh+h0 (full coverage);
    // slot 3: xi GEMM; slot 4: rnn_hmma (the ncu-profiled slot).
    reset_kernel<<<1, 256>>>();
    split_all_kernel<<<SPLIT_WH_BLOCKS + SPLIT_H0_BLOCKS, 256>>>(Wh, h0);
    gemm_xi_kernel<<<dim3(H_DIM / 128, M1 / 128), 256>>>(x, Wi, bi, bh, out);
    rnn_hmma<<<dim3(32, 4), 256, SMEM_P2>>>(out);
}